// round 2
// baseline (speedup 1.0000x reference)
#include <cuda_runtime.h>

#define HDIM   256
#define DK     64
#define NHEADS 4
#define TQ     1024
#define NMAX   24576
#define BTMAX  16384
#define BMAX   64

// ---- scratch (device globals: allocation-free) ----
__device__ float g_Q[TQ * HDIM];
__device__ float g_K[NMAX * HDIM];
__device__ float g_V[NMAX * HDIM];
__device__ float g_ctx[BTMAX * HDIM];
__device__ int   g_starts[BMAX];
__device__ int   g_lens[BMAX];

// ---- setup: compute segment starts; auto-detect int32 vs int64 lengths ----
__global__ void setup_kernel(const int* __restrict__ lens_raw, int B, int N) {
    if (threadIdx.x != 0 || blockIdx.x != 0) return;
    long long s32 = 0;
    for (int b = 0; b < B; b++) s32 += lens_raw[b];
    int acc = 0;
    if (s32 == (long long)N) {
        for (int b = 0; b < B; b++) { g_starts[b] = acc; g_lens[b] = lens_raw[b]; acc += lens_raw[b]; }
    } else {
        const long long* l64 = (const long long*)lens_raw;
        for (int b = 0; b < B; b++) { int L = (int)l64[b]; g_starts[b] = acc; g_lens[b] = L; acc += L; }
    }
}

// ---- generic Y = X @ W^T GEMM (optionally two weights sharing X loads) ----
// X: [M,256] row-major, W: [256,256] row-major (torch Linear weight), Y: [M,256]
// block tile 64x64, 256 threads, 4x4 microtile, k-step 16, transposed smem staging.
template <bool DUAL>
__global__ void __launch_bounds__(256) gemm_xwT(
    const float* __restrict__ X,
    const float* __restrict__ W0, const float* __restrict__ W1,
    float* __restrict__ Y0, float* __restrict__ Y1)
{
    __shared__ float Xs [16][68];
    __shared__ float Ws0[16][68];
    __shared__ float Ws1[16][68];

    const int tid = threadIdx.x;
    const int tx = tid & 15, ty = tid >> 4;
    const int m0 = blockIdx.x * 64;
    const int n0 = blockIdx.y * 64;
    const int lr = tid >> 2;          // 0..63 : row within 64-row tile
    const int lk = (tid & 3) * 4;     // 0,4,8,12 : k offset within 16-wide k-tile

    float c0[4][4] = {};
    float c1[4][4] = {};

    for (int k0 = 0; k0 < HDIM; k0 += 16) {
        float4 xv  = *(const float4*)&X [(m0 + lr) * HDIM + k0 + lk];
        float4 wv0 = *(const float4*)&W0[(n0 + lr) * HDIM + k0 + lk];
        float4 wv1;
        if (DUAL) wv1 = *(const float4*)&W1[(n0 + lr) * HDIM + k0 + lk];
        __syncthreads();
        Xs [lk + 0][lr] = xv.x;  Xs [lk + 1][lr] = xv.y;  Xs [lk + 2][lr] = xv.z;  Xs [lk + 3][lr] = xv.w;
        Ws0[lk + 0][lr] = wv0.x; Ws0[lk + 1][lr] = wv0.y; Ws0[lk + 2][lr] = wv0.z; Ws0[lk + 3][lr] = wv0.w;
        if (DUAL) {
            Ws1[lk + 0][lr] = wv1.x; Ws1[lk + 1][lr] = wv1.y; Ws1[lk + 2][lr] = wv1.z; Ws1[lk + 3][lr] = wv1.w;
        }
        __syncthreads();

        #pragma unroll
        for (int kk = 0; kk < 16; kk++) {
            float4 a  = *(const float4*)&Xs [kk][ty * 4];
            float4 b0 = *(const float4*)&Ws0[kk][tx * 4];
            float av[4] = {a.x, a.y, a.z, a.w};
            float b0v[4] = {b0.x, b0.y, b0.z, b0.w};
            #pragma unroll
            for (int r = 0; r < 4; r++)
                #pragma unroll
                for (int c = 0; c < 4; c++)
                    c0[r][c] += av[r] * b0v[c];
            if (DUAL) {
                float4 b1 = *(const float4*)&Ws1[kk][tx * 4];
                float b1v[4] = {b1.x, b1.y, b1.z, b1.w};
                #pragma unroll
                for (int r = 0; r < 4; r++)
                    #pragma unroll
                    for (int c = 0; c < 4; c++)
                        c1[r][c] += av[r] * b1v[c];
            }
        }
    }

    #pragma unroll
    for (int r = 0; r < 4; r++) {
        float4 o0 = make_float4(c0[r][0], c0[r][1], c0[r][2], c0[r][3]);
        *(float4*)&Y0[(m0 + ty * 4 + r) * HDIM + n0 + tx * 4] = o0;
        if (DUAL) {
            float4 o1 = make_float4(c1[r][0], c1[r][1], c1[r][2], c1[r][3]);
            *(float4*)&Y1[(m0 + ty * 4 + r) * HDIM + n0 + tx * 4] = o1;
        }
    }
}

// ---- flash-attention over ragged segments ----
// grid: (T/64, NHEADS, B). block: 256 threads (tx 0..15, ty 0..15), 4x4 microtiles.
// smem: Qs[d][i] (transposed), Ks[d][j] (transposed, aliased by Ps[l][i]), Vs[l][c].
__global__ void __launch_bounds__(256) attn_kernel(int T)
{
    extern __shared__ float sm[];
    float (*Qs)[68] = (float(*)[68])(sm);
    float (*Ks)[68] = (float(*)[68])(sm + 64 * 68);        // aliased as Ps after S
    float (*Vs)[68] = (float(*)[68])(sm + 2 * 64 * 68);

    const int t0 = blockIdx.x * 64;
    const int h  = blockIdx.y;
    const int b  = blockIdx.z;
    const int start = g_starts[b];
    const int L     = g_lens[b];

    const int tid = threadIdx.x;
    const int tx = tid & 15, ty = tid >> 4;
    const int lr = tid >> 2;
    const int lk = (tid & 3) * 4;

    // load Q tile transposed: Qs[d][i]
    #pragma unroll
    for (int p = 0; p < 4; p++) {
        int d = p * 16 + lk;
        float4 q = *(const float4*)&g_Q[(t0 + lr) * HDIM + h * DK + d];
        Qs[d + 0][lr] = q.x; Qs[d + 1][lr] = q.y; Qs[d + 2][lr] = q.z; Qs[d + 3][lr] = q.w;
    }

    float o[4][4];
    float m[4], l[4];
    #pragma unroll
    for (int r = 0; r < 4; r++) {
        m[r] = -1e30f; l[r] = 0.f;
        #pragma unroll
        for (int c = 0; c < 4; c++) o[r][c] = 0.f;
    }

    const float sc = 0.125f;   // 1/sqrt(DK)/TEMP

    for (int l0 = 0; l0 < L; l0 += 64) {
        __syncthreads();       // previous PV reads done before overwriting Ks/Vs
        #pragma unroll
        for (int p = 0; p < 4; p++) {
            int d = p * 16 + lk;
            int li = l0 + lr; if (li > L - 1) li = L - 1;   // clamp (safety)
            int node = start + li;
            float4 kv = *(const float4*)&g_K[node * HDIM + h * DK + d];
            Ks[d + 0][lr] = kv.x; Ks[d + 1][lr] = kv.y; Ks[d + 2][lr] = kv.z; Ks[d + 3][lr] = kv.w;
            float4 vv = *(const float4*)&g_V[node * HDIM + h * DK + d];
            *(float4*)&Vs[lr][d] = vv;
        }
        __syncthreads();

        // S = Q_tile @ K_chunk^T
        float s[4][4] = {};
        #pragma unroll 8
        for (int d = 0; d < 64; d++) {
            float4 a  = *(const float4*)&Qs[d][ty * 4];
            float4 bk = *(const float4*)&Ks[d][tx * 4];
            float av[4] = {a.x, a.y, a.z, a.w};
            float bv[4] = {bk.x, bk.y, bk.z, bk.w};
            #pragma unroll
            for (int r = 0; r < 4; r++)
                #pragma unroll
                for (int c = 0; c < 4; c++)
                    s[r][c] += av[r] * bv[c];
        }

        // scale + mask
        const bool tail = (l0 + 64 > L);
        #pragma unroll
        for (int r = 0; r < 4; r++)
            #pragma unroll
            for (int c = 0; c < 4; c++) {
                float v = s[r][c] * sc;
                if (tail && (l0 + tx * 4 + c >= L)) v = -1e30f;
                s[r][c] = v;
            }

        // online softmax (row stats shared across the 16 tx lanes of each ty)
        #pragma unroll
        for (int r = 0; r < 4; r++) {
            float mx = fmaxf(fmaxf(s[r][0], s[r][1]), fmaxf(s[r][2], s[r][3]));
            #pragma unroll
            for (int off = 8; off; off >>= 1)
                mx = fmaxf(mx, __shfl_xor_sync(0xffffffffu, mx, off));
            float mn = fmaxf(m[r], mx);
            float sf = __expf(m[r] - mn);
            float rs = 0.f;
            #pragma unroll
            for (int c = 0; c < 4; c++) { s[r][c] = __expf(s[r][c] - mn); rs += s[r][c]; }
            #pragma unroll
            for (int off = 8; off; off >>= 1)
                rs += __shfl_xor_sync(0xffffffffu, rs, off);
            m[r] = mn;
            l[r] = l[r] * sf + rs;
            #pragma unroll
            for (int c = 0; c < 4; c++) o[r][c] *= sf;
        }

        __syncthreads();       // all S reads of Ks finished
        // store P transposed into Ks alias: Ps[lcol][qrow]
        #pragma unroll
        for (int r = 0; r < 4; r++)
            #pragma unroll
            for (int c = 0; c < 4; c++)
                Ks[tx * 4 + c][ty * 4 + r] = s[r][c];
        __syncthreads();

        // O += P @ V
        #pragma unroll 8
        for (int d = 0; d < 64; d++) {
            float4 a  = *(const float4*)&Ks[d][ty * 4];  // P[i..i+3][d]
            float4 bv = *(const float4*)&Vs[d][tx * 4];  // V[d][c..c+3]
            float av[4] = {a.x, a.y, a.z, a.w};
            float vv[4] = {bv.x, bv.y, bv.z, bv.w};
            #pragma unroll
            for (int r = 0; r < 4; r++)
                #pragma unroll
                for (int c = 0; c < 4; c++)
                    o[r][c] += av[r] * vv[c];
        }
    }

    // epilogue: normalize and write ctx [b*T + t][h*DK + c]
    #pragma unroll
    for (int r = 0; r < 4; r++) {
        float inv = 1.f / l[r];
        float4 w = make_float4(o[r][0] * inv, o[r][1] * inv, o[r][2] * inv, o[r][3] * inv);
        int row = b * T + t0 + ty * 4 + r;
        *(float4*)&g_ctx[row * HDIM + h * DK + tx * 4] = w;
    }
}

extern "C" void kernel_launch(void* const* d_in, const int* in_sizes, int n_in,
                              void* d_out, int out_size)
{
    const float* go   = (const float*)d_in[0];
    const float* node = (const float*)d_in[1];
    const float* Wq   = (const float*)d_in[2];
    const float* Wk   = (const float*)d_in[3];
    const float* Wv   = (const float*)d_in[4];
    const float* Wp   = (const float*)d_in[5];
    const int*   lens = (const int*)d_in[6];
    float* out = (float*)d_out;

    const int T = in_sizes[0] / HDIM;   // 1024
    const int N = in_sizes[1] / HDIM;   // 24576
    const int B = in_sizes[6];          // 16

    float *pQ, *pK, *pV, *pC;
    cudaGetSymbolAddress((void**)&pQ, g_Q);
    cudaGetSymbolAddress((void**)&pK, g_K);
    cudaGetSymbolAddress((void**)&pV, g_V);
    cudaGetSymbolAddress((void**)&pC, g_ctx);

    setup_kernel<<<1, 32>>>(lens, B, N);

    dim3 blk(256);
    // Q = go @ Wq^T
    gemm_xwT<false><<<dim3(T / 64, 4), blk>>>(go, Wq, nullptr, pQ, nullptr);
    // K, V = node_h @ {Wk,Wv}^T (fused: shared X loads)
    gemm_xwT<true><<<dim3(N / 64, 4), blk>>>(node, Wk, Wv, pK, pV);

    // attention
    int smem = 3 * 64 * 68 * (int)sizeof(float);   // 52224 B
    cudaFuncSetAttribute(attn_kernel, cudaFuncAttributeMaxDynamicSharedMemorySize, smem);
    attn_kernel<<<dim3(T / 64, NHEADS, B), blk, smem>>>(T);

    // out = ctx @ Wproj^T
    gemm_xwT<false><<<dim3((B * T) / 64, 4), blk>>>(pC, Wp, nullptr, out, nullptr);
}

// round 4
// speedup vs baseline: 1.0176x; 1.0176x over previous
#include <cuda_runtime.h>

#define HDIM   256
#define DK     64
#define NHEADS 4
#define TQ     1024
#define NMAX   24576
#define BTMAX  16384
#define BMAX   64

// ---- scratch (device globals: allocation-free) ----
__device__ float g_Q[TQ * HDIM];
__device__ float g_K[NMAX * HDIM];
__device__ float g_V[NMAX * HDIM];
__device__ float g_ctx[BTMAX * HDIM];
__device__ int   g_starts[BMAX];
__device__ int   g_lens[BMAX];

// ---- setup: compute segment starts; auto-detect int32 vs int64 lengths ----
__global__ void setup_kernel(const int* __restrict__ lens_raw, int B, int N) {
    if (threadIdx.x != 0 || blockIdx.x != 0) return;
    long long s32 = 0;
    for (int b = 0; b < B; b++) s32 += lens_raw[b];
    int acc = 0;
    if (s32 == (long long)N) {
        for (int b = 0; b < B; b++) { g_starts[b] = acc; g_lens[b] = lens_raw[b]; acc += lens_raw[b]; }
    } else {
        const long long* l64 = (const long long*)lens_raw;
        for (int b = 0; b < B; b++) { int L = (int)l64[b]; g_starts[b] = acc; g_lens[b] = L; acc += L; }
    }
}

// ================= GEMM: Y = X @ W^T, 128x128 tile, split 8x8 microtile ======
// X [M,256], W [256,256] row-major, Y [M,256]. 256 threads. k-step 16.
__global__ void __launch_bounds__(256, 2) gemm128(
    const float* __restrict__ X, const float* __restrict__ W, float* __restrict__ Y)
{
    __shared__ float Xs[16][132];
    __shared__ float Ws[16][132];

    const int tid = threadIdx.x;
    const int tx = tid & 15, ty = tid >> 4;
    const int m0 = blockIdx.x * 128;
    const int n0 = blockIdx.y * 128;
    const int lr = tid & 127;          // 0..127 row in tile
    const int lc = (tid >> 7) * 8;     // 0 or 8 : k offset

    float acc[8][8] = {};

    for (int k0 = 0; k0 < HDIM; k0 += 16) {
        float4 x0 = *(const float4*)&X[(m0 + lr) * HDIM + k0 + lc];
        float4 x1 = *(const float4*)&X[(m0 + lr) * HDIM + k0 + lc + 4];
        float4 w0 = *(const float4*)&W[(n0 + lr) * HDIM + k0 + lc];
        float4 w1 = *(const float4*)&W[(n0 + lr) * HDIM + k0 + lc + 4];
        __syncthreads();
        Xs[lc + 0][lr] = x0.x; Xs[lc + 1][lr] = x0.y; Xs[lc + 2][lr] = x0.z; Xs[lc + 3][lr] = x0.w;
        Xs[lc + 4][lr] = x1.x; Xs[lc + 5][lr] = x1.y; Xs[lc + 6][lr] = x1.z; Xs[lc + 7][lr] = x1.w;
        Ws[lc + 0][lr] = w0.x; Ws[lc + 1][lr] = w0.y; Ws[lc + 2][lr] = w0.z; Ws[lc + 3][lr] = w0.w;
        Ws[lc + 4][lr] = w1.x; Ws[lc + 5][lr] = w1.y; Ws[lc + 6][lr] = w1.z; Ws[lc + 7][lr] = w1.w;
        __syncthreads();

        #pragma unroll
        for (int kk = 0; kk < 16; kk++) {
            float4 a0 = *(const float4*)&Xs[kk][ty * 4];
            float4 a1 = *(const float4*)&Xs[kk][64 + ty * 4];
            float4 b0 = *(const float4*)&Ws[kk][tx * 4];
            float4 b1 = *(const float4*)&Ws[kk][64 + tx * 4];
            float av[8] = {a0.x, a0.y, a0.z, a0.w, a1.x, a1.y, a1.z, a1.w};
            float bv[8] = {b0.x, b0.y, b0.z, b0.w, b1.x, b1.y, b1.z, b1.w};
            #pragma unroll
            for (int r = 0; r < 8; r++)
                #pragma unroll
                for (int c = 0; c < 8; c++)
                    acc[r][c] += av[r] * bv[c];
        }
    }

    #pragma unroll
    for (int i = 0; i < 8; i++) {
        int row = m0 + ((i < 4) ? (ty * 4 + i) : (64 + ty * 4 + i - 4));
        *(float4*)&Y[row * HDIM + n0 + tx * 4]      = make_float4(acc[i][0], acc[i][1], acc[i][2], acc[i][3]);
        *(float4*)&Y[row * HDIM + n0 + 64 + tx * 4] = make_float4(acc[i][4], acc[i][5], acc[i][6], acc[i][7]);
    }
}

// ================= flash attention over ragged segments =====================
// grid: (T/128, NHEADS, B), block 256. S-tile 128q x 128k, split 8x8 microtile.
// smem: Qs[64][132] (d-major), Ks[64][132] (d-major), Vs[128][68], Ps[128][132] (swizzled)
__global__ void __launch_bounds__(256) attn_kernel(int T)
{
    extern __shared__ float sm[];
    float (*Qs)[132] = (float(*)[132])(sm);
    float (*Ks)[132] = (float(*)[132])(sm + 64 * 132);
    float (*Vs)[68]  = (float(*)[68]) (sm + 2 * 64 * 132);
    float (*Ps)[132] = (float(*)[132])(sm + 2 * 64 * 132 + 128 * 68);

    const int t0 = blockIdx.x * 128;
    const int h  = blockIdx.y;
    const int b  = blockIdx.z;
    const int start = g_starts[b];
    const int L     = g_lens[b];

    const int tid = threadIdx.x;
    const int tx = tid & 15, ty = tid >> 4;
    const int lr = tid & 127;           // loader row
    const int ld = (tid >> 7) * 32;     // loader d-offset (0 or 32)

    // load Q tile transposed: Qs[d][q]
    #pragma unroll
    for (int p = 0; p < 8; p++) {
        float4 q = *(const float4*)&g_Q[(t0 + lr) * HDIM + h * DK + ld + p * 4];
        Qs[ld + p * 4 + 0][lr] = q.x; Qs[ld + p * 4 + 1][lr] = q.y;
        Qs[ld + p * 4 + 2][lr] = q.z; Qs[ld + p * 4 + 3][lr] = q.w;
    }

    float o[8][4];
    float m[8], l[8];
    #pragma unroll
    for (int i = 0; i < 8; i++) {
        m[i] = -1e30f; l[i] = 0.f;
        #pragma unroll
        for (int j = 0; j < 4; j++) o[i][j] = 0.f;
    }

    const float sc = 0.125f;   // 1/sqrt(DK)/TEMP

    for (int l0 = 0; l0 < L; l0 += 128) {
        __syncthreads();   // prior PV reads of Vs/Ps complete; prior S reads of Ks complete
        // load K,V chunk (128 keys x 64 d)
        {
            int li = l0 + lr; if (li > L - 1) li = L - 1;
            int node = start + li;
            #pragma unroll
            for (int p = 0; p < 8; p++) {
                float4 kv = *(const float4*)&g_K[node * HDIM + h * DK + ld + p * 4];
                Ks[ld + p * 4 + 0][lr] = kv.x; Ks[ld + p * 4 + 1][lr] = kv.y;
                Ks[ld + p * 4 + 2][lr] = kv.z; Ks[ld + p * 4 + 3][lr] = kv.w;
                float4 vv = *(const float4*)&g_V[node * HDIM + h * DK + ld + p * 4];
                *(float4*)&Vs[lr][ld + p * 4] = vv;
            }
        }
        __syncthreads();

        // S = Q @ K^T : split 8x8 microtile
        float s[8][8] = {};
        #pragma unroll 8
        for (int d = 0; d < 64; d++) {
            float4 a0 = *(const float4*)&Qs[d][ty * 4];
            float4 a1 = *(const float4*)&Qs[d][64 + ty * 4];
            float4 b0 = *(const float4*)&Ks[d][tx * 4];
            float4 b1 = *(const float4*)&Ks[d][64 + tx * 4];
            float av[8] = {a0.x, a0.y, a0.z, a0.w, a1.x, a1.y, a1.z, a1.w};
            float bv[8] = {b0.x, b0.y, b0.z, b0.w, b1.x, b1.y, b1.z, b1.w};
            #pragma unroll
            for (int r = 0; r < 8; r++)
                #pragma unroll
                for (int c = 0; c < 8; c++)
                    s[r][c] += av[r] * bv[c];
        }

        // scale + ragged tail mask
        const bool tail = (l0 + 128 > L);
        #pragma unroll
        for (int i = 0; i < 8; i++)
            #pragma unroll
            for (int j = 0; j < 8; j++) {
                float v = s[i][j] * sc;
                if (tail) {
                    int col = l0 + ((j < 4) ? (tx * 4 + j) : (64 + tx * 4 + j - 4));
                    if (col >= L) v = -1e30f;
                }
                s[i][j] = v;
            }

        // online softmax per row (stats shared across the 16 tx lanes per half-warp)
        #pragma unroll
        for (int i = 0; i < 8; i++) {
            float mx = s[i][0];
            #pragma unroll
            for (int j = 1; j < 8; j++) mx = fmaxf(mx, s[i][j]);
            #pragma unroll
            for (int off = 8; off; off >>= 1)
                mx = fmaxf(mx, __shfl_xor_sync(0xffffffffu, mx, off));
            float mn = fmaxf(m[i], mx);
            float sf = __expf(m[i] - mn);
            float rs = 0.f;
            #pragma unroll
            for (int j = 0; j < 8; j++) { s[i][j] = __expf(s[i][j] - mn); rs += s[i][j]; }
            #pragma unroll
            for (int off = 8; off; off >>= 1)
                rs += __shfl_xor_sync(0xffffffffu, rs, off);
            m[i] = mn;
            l[i] = l[i] * sf + rs;
            #pragma unroll
            for (int j = 0; j < 4; j++) o[i][j] *= sf;
        }

        // store P transposed with XOR swizzle: Ps[key][ q ^ f(key) ]
        #pragma unroll
        for (int j = 0; j < 8; j++) {
            int c = (j < 4) ? (tx * 4 + j) : (64 + tx * 4 + j - 4);
            int f = ((c >> 3) & 3) << 2;
            int r0 = (ty * 4) ^ f;
            *(float4*)&Ps[c][r0]      = make_float4(s[0][j], s[1][j], s[2][j], s[3][j]);
            *(float4*)&Ps[c][64 + r0] = make_float4(s[4][j], s[5][j], s[6][j], s[7][j]);
        }
        __syncthreads();

        // O += P @ V
        #pragma unroll 4
        for (int kl = 0; kl < 128; kl++) {
            int sr = (ty * 4) ^ (((kl >> 3) & 3) << 2);
            float4 a0 = *(const float4*)&Ps[kl][sr];
            float4 a1 = *(const float4*)&Ps[kl][64 + sr];
            float4 bv = *(const float4*)&Vs[kl][tx * 4];
            float av[8] = {a0.x, a0.y, a0.z, a0.w, a1.x, a1.y, a1.z, a1.w};
            float vv[4] = {bv.x, bv.y, bv.z, bv.w};
            #pragma unroll
            for (int r = 0; r < 8; r++)
                #pragma unroll
                for (int c = 0; c < 4; c++)
                    o[r][c] += av[r] * vv[c];
        }
    }

    // epilogue: normalize, write ctx
    #pragma unroll
    for (int i = 0; i < 8; i++) {
        int r = (i < 4) ? (ty * 4 + i) : (64 + ty * 4 + i - 4);
        float inv = 1.f / l[i];
        int row = b * T + t0 + r;
        *(float4*)&g_ctx[row * HDIM + h * DK + tx * 4] =
            make_float4(o[i][0] * inv, o[i][1] * inv, o[i][2] * inv, o[i][3] * inv);
    }
}

extern "C" void kernel_launch(void* const* d_in, const int* in_sizes, int n_in,
                              void* d_out, int out_size)
{
    const float* go   = (const float*)d_in[0];
    const float* node = (const float*)d_in[1];
    const float* Wq   = (const float*)d_in[2];
    const float* Wk   = (const float*)d_in[3];
    const float* Wv   = (const float*)d_in[4];
    const float* Wp   = (const float*)d_in[5];
    const int*   lens = (const int*)d_in[6];
    float* out = (float*)d_out;

    const int T = in_sizes[0] / HDIM;   // 1024
    const int N = in_sizes[1] / HDIM;   // 24576
    const int B = in_sizes[6];          // 16

    float *pQ, *pK, *pV, *pC;
    cudaGetSymbolAddress((void**)&pQ, g_Q);
    cudaGetSymbolAddress((void**)&pK, g_K);
    cudaGetSymbolAddress((void**)&pV, g_V);
    cudaGetSymbolAddress((void**)&pC, g_ctx);

    setup_kernel<<<1, 32>>>(lens, B, N);

    dim3 blk(256);
    gemm128<<<dim3(T / 128, 2), blk>>>(go, Wq, pQ);
    gemm128<<<dim3(N / 128, 2), blk>>>(node, Wk, pK);
    gemm128<<<dim3(N / 128, 2), blk>>>(node, Wv, pV);

    int smem = (2 * 64 * 132 + 128 * 68 + 128 * 132) * (int)sizeof(float);   // 169984 B
    cudaFuncSetAttribute(attn_kernel, cudaFuncAttributeMaxDynamicSharedMemorySize, smem);
    attn_kernel<<<dim3(T / 128, NHEADS, B), blk, smem>>>(T);

    gemm128<<<dim3((B * T) / 128, 2), blk>>>(pC, Wp, out);
}

// round 5
// speedup vs baseline: 1.0879x; 1.0690x over previous
#include <cuda_runtime.h>

#define HDIM   256
#define DK     64
#define NHEADS 4
#define TQ     1024
#define NMAX   24576
#define BTMAX  16384
#define BMAX   64

// ---- scratch (device globals: allocation-free) ----
__device__ float g_Q[TQ * HDIM];
__device__ float g_K[NMAX * HDIM];
__device__ float g_V[NMAX * HDIM];
__device__ float g_ctx[BTMAX * HDIM];
__device__ int   g_starts[BMAX];
__device__ int   g_lens[BMAX];

// ---- packed f32x2 helpers (Blackwell FFMA2 path; ptxas won't auto-fuse) ----
typedef unsigned long long u64;

__device__ __forceinline__ u64 bcast2(float v) {
    u64 r; asm("mov.b64 %0, {%1, %1};" : "=l"(r) : "f"(v)); return r;
}
__device__ __forceinline__ float2 unpack2(u64 v) {
    float2 r; asm("mov.b64 {%0, %1}, %2;" : "=f"(r.x), "=f"(r.y) : "l"(v)); return r;
}
#define FMA2(d, a, b) asm("fma.rn.f32x2 %0, %1, %2, %0;" : "+l"(d) : "l"(a), "l"(b))

// ---- setup: compute segment starts; auto-detect int32 vs int64 lengths ----
__global__ void setup_kernel(const int* __restrict__ lens_raw, int B, int N) {
    if (threadIdx.x != 0 || blockIdx.x != 0) return;
    long long s32 = 0;
    for (int b = 0; b < B; b++) s32 += lens_raw[b];
    int acc = 0;
    if (s32 == (long long)N) {
        for (int b = 0; b < B; b++) { g_starts[b] = acc; g_lens[b] = lens_raw[b]; acc += lens_raw[b]; }
    } else {
        const long long* l64 = (const long long*)lens_raw;
        for (int b = 0; b < B; b++) { int L = (int)l64[b]; g_starts[b] = acc; g_lens[b] = L; acc += L; }
    }
}

// ================= GEMM: Y = X @ W^T, 128x128 tile, split 8x8 microtile =====
// packed f32x2 accumulators: acc2[r][p] holds columns (2p, 2p+1) of the 8-wide
// split microtile (cols: tx*4..tx*4+3 and 64+tx*4..64+tx*4+3).
__global__ void __launch_bounds__(256, 2) gemm128(
    const float* __restrict__ X, const float* __restrict__ W, float* __restrict__ Y)
{
    __shared__ float Xs[16][132];
    __shared__ float Ws[16][132];

    const int tid = threadIdx.x;
    const int tx = tid & 15, ty = tid >> 4;
    const int m0 = blockIdx.x * 128;
    const int n0 = blockIdx.y * 128;
    const int lr = tid & 127;
    const int lc = (tid >> 7) * 8;

    u64 acc2[8][4];
    #pragma unroll
    for (int r = 0; r < 8; r++)
        #pragma unroll
        for (int p = 0; p < 4; p++) acc2[r][p] = 0ull;   // (0.0f, 0.0f)

    for (int k0 = 0; k0 < HDIM; k0 += 16) {
        float4 x0 = *(const float4*)&X[(m0 + lr) * HDIM + k0 + lc];
        float4 x1 = *(const float4*)&X[(m0 + lr) * HDIM + k0 + lc + 4];
        float4 w0 = *(const float4*)&W[(n0 + lr) * HDIM + k0 + lc];
        float4 w1 = *(const float4*)&W[(n0 + lr) * HDIM + k0 + lc + 4];
        __syncthreads();
        Xs[lc + 0][lr] = x0.x; Xs[lc + 1][lr] = x0.y; Xs[lc + 2][lr] = x0.z; Xs[lc + 3][lr] = x0.w;
        Xs[lc + 4][lr] = x1.x; Xs[lc + 5][lr] = x1.y; Xs[lc + 6][lr] = x1.z; Xs[lc + 7][lr] = x1.w;
        Ws[lc + 0][lr] = w0.x; Ws[lc + 1][lr] = w0.y; Ws[lc + 2][lr] = w0.z; Ws[lc + 3][lr] = w0.w;
        Ws[lc + 4][lr] = w1.x; Ws[lc + 5][lr] = w1.y; Ws[lc + 6][lr] = w1.z; Ws[lc + 7][lr] = w1.w;
        __syncthreads();

        #pragma unroll
        for (int kk = 0; kk < 16; kk++) {
            float4 a0 = *(const float4*)&Xs[kk][ty * 4];
            float4 a1 = *(const float4*)&Xs[kk][64 + ty * 4];
            ulonglong2 b0 = *(const ulonglong2*)&Ws[kk][tx * 4];
            ulonglong2 b1 = *(const ulonglong2*)&Ws[kk][64 + tx * 4];
            float av[8] = {a0.x, a0.y, a0.z, a0.w, a1.x, a1.y, a1.z, a1.w};
            u64 bb[4] = {b0.x, b0.y, b1.x, b1.y};
            #pragma unroll
            for (int r = 0; r < 8; r++) {
                u64 ar = bcast2(av[r]);
                #pragma unroll
                for (int p = 0; p < 4; p++) FMA2(acc2[r][p], ar, bb[p]);
            }
        }
    }

    #pragma unroll
    for (int i = 0; i < 8; i++) {
        int row = m0 + ((i < 4) ? (ty * 4 + i) : (64 + ty * 4 + i - 4));
        *(ulonglong2*)&Y[row * HDIM + n0 + tx * 4]      = make_ulonglong2(acc2[i][0], acc2[i][1]);
        *(ulonglong2*)&Y[row * HDIM + n0 + 64 + tx * 4] = make_ulonglong2(acc2[i][2], acc2[i][3]);
    }
}

// ================= flash attention over ragged segments =====================
__global__ void __launch_bounds__(256) attn_kernel(int T)
{
    extern __shared__ float sm[];
    float (*Qs)[132] = (float(*)[132])(sm);
    float (*Ks)[132] = (float(*)[132])(sm + 64 * 132);
    float (*Vs)[68]  = (float(*)[68]) (sm + 2 * 64 * 132);
    float (*Ps)[132] = (float(*)[132])(sm + 2 * 64 * 132 + 128 * 68);

    const int t0 = blockIdx.x * 128;
    const int h  = blockIdx.y;
    const int b  = blockIdx.z;
    const int start = g_starts[b];
    const int L     = g_lens[b];

    const int tid = threadIdx.x;
    const int tx = tid & 15, ty = tid >> 4;
    const int lr = tid & 127;
    const int ld = (tid >> 7) * 32;

    #pragma unroll
    for (int p = 0; p < 8; p++) {
        float4 q = *(const float4*)&g_Q[(t0 + lr) * HDIM + h * DK + ld + p * 4];
        Qs[ld + p * 4 + 0][lr] = q.x; Qs[ld + p * 4 + 1][lr] = q.y;
        Qs[ld + p * 4 + 2][lr] = q.z; Qs[ld + p * 4 + 3][lr] = q.w;
    }

    u64 o2[8][2];
    float m[8], l[8];
    #pragma unroll
    for (int i = 0; i < 8; i++) {
        m[i] = -1e30f; l[i] = 0.f;
        o2[i][0] = 0ull; o2[i][1] = 0ull;
    }

    const float sc = 0.125f;   // 1/sqrt(DK)/TEMP

    for (int l0 = 0; l0 < L; l0 += 128) {
        __syncthreads();
        {
            int li = l0 + lr; if (li > L - 1) li = L - 1;
            int node = start + li;
            #pragma unroll
            for (int p = 0; p < 8; p++) {
                float4 kv = *(const float4*)&g_K[node * HDIM + h * DK + ld + p * 4];
                Ks[ld + p * 4 + 0][lr] = kv.x; Ks[ld + p * 4 + 1][lr] = kv.y;
                Ks[ld + p * 4 + 2][lr] = kv.z; Ks[ld + p * 4 + 3][lr] = kv.w;
                float4 vv = *(const float4*)&g_V[node * HDIM + h * DK + ld + p * 4];
                *(float4*)&Vs[lr][ld + p * 4] = vv;
            }
        }
        __syncthreads();

        // S = Q @ K^T, packed f32x2
        u64 s2[8][4];
        #pragma unroll
        for (int r = 0; r < 8; r++)
            #pragma unroll
            for (int p = 0; p < 4; p++) s2[r][p] = 0ull;

        #pragma unroll 8
        for (int d = 0; d < 64; d++) {
            float4 a0 = *(const float4*)&Qs[d][ty * 4];
            float4 a1 = *(const float4*)&Qs[d][64 + ty * 4];
            ulonglong2 b0 = *(const ulonglong2*)&Ks[d][tx * 4];
            ulonglong2 b1 = *(const ulonglong2*)&Ks[d][64 + tx * 4];
            float av[8] = {a0.x, a0.y, a0.z, a0.w, a1.x, a1.y, a1.z, a1.w};
            u64 bb[4] = {b0.x, b0.y, b1.x, b1.y};
            #pragma unroll
            for (int r = 0; r < 8; r++) {
                u64 ar = bcast2(av[r]);
                #pragma unroll
                for (int p = 0; p < 4; p++) FMA2(s2[r][p], ar, bb[p]);
            }
        }

        // unpack, scale + ragged tail mask
        float s[8][8];
        #pragma unroll
        for (int r = 0; r < 8; r++)
            #pragma unroll
            for (int p = 0; p < 4; p++) {
                float2 u = unpack2(s2[r][p]);
                s[r][p * 2] = u.x; s[r][p * 2 + 1] = u.y;
            }

        const bool tail = (l0 + 128 > L);
        #pragma unroll
        for (int i = 0; i < 8; i++)
            #pragma unroll
            for (int j = 0; j < 8; j++) {
                float v = s[i][j] * sc;
                if (tail) {
                    int col = l0 + ((j < 4) ? (tx * 4 + j) : (64 + tx * 4 + j - 4));
                    if (col >= L) v = -1e30f;
                }
                s[i][j] = v;
            }

        // online softmax per row
        float sf[8];
        #pragma unroll
        for (int i = 0; i < 8; i++) {
            float mx = s[i][0];
            #pragma unroll
            for (int j = 1; j < 8; j++) mx = fmaxf(mx, s[i][j]);
            #pragma unroll
            for (int off = 8; off; off >>= 1)
                mx = fmaxf(mx, __shfl_xor_sync(0xffffffffu, mx, off));
            float mn = fmaxf(m[i], mx);
            sf[i] = __expf(m[i] - mn);
            float rs = 0.f;
            #pragma unroll
            for (int j = 0; j < 8; j++) { s[i][j] = __expf(s[i][j] - mn); rs += s[i][j]; }
            #pragma unroll
            for (int off = 8; off; off >>= 1)
                rs += __shfl_xor_sync(0xffffffffu, rs, off);
            m[i] = mn;
            l[i] = l[i] * sf[i] + rs;
        }
        // rescale packed O accumulators
        #pragma unroll
        for (int i = 0; i < 8; i++) {
            u64 fi = bcast2(sf[i]);
            u64 z0 = 0ull, z1 = 0ull;
            FMA2(z0, o2[i][0], fi); FMA2(z1, o2[i][1], fi);
            o2[i][0] = z0; o2[i][1] = z1;
        }

        // store P transposed with XOR swizzle
        #pragma unroll
        for (int j = 0; j < 8; j++) {
            int c = (j < 4) ? (tx * 4 + j) : (64 + tx * 4 + j - 4);
            int f = ((c >> 3) & 3) << 2;
            int r0 = (ty * 4) ^ f;
            *(float4*)&Ps[c][r0]      = make_float4(s[0][j], s[1][j], s[2][j], s[3][j]);
            *(float4*)&Ps[c][64 + r0] = make_float4(s[4][j], s[5][j], s[6][j], s[7][j]);
        }
        __syncthreads();

        // O += P @ V, packed f32x2
        #pragma unroll 4
        for (int kl = 0; kl < 128; kl++) {
            int sr = (ty * 4) ^ (((kl >> 3) & 3) << 2);
            float4 a0 = *(const float4*)&Ps[kl][sr];
            float4 a1 = *(const float4*)&Ps[kl][64 + sr];
            ulonglong2 bv = *(const ulonglong2*)&Vs[kl][tx * 4];
            float av[8] = {a0.x, a0.y, a0.z, a0.w, a1.x, a1.y, a1.z, a1.w};
            #pragma unroll
            for (int r = 0; r < 8; r++) {
                u64 ar = bcast2(av[r]);
                FMA2(o2[r][0], ar, bv.x);
                FMA2(o2[r][1], ar, bv.y);
            }
        }
    }

    // epilogue: normalize, write ctx
    #pragma unroll
    for (int i = 0; i < 8; i++) {
        int r = (i < 4) ? (ty * 4 + i) : (64 + ty * 4 + i - 4);
        float inv = 1.f / l[i];
        float2 p0 = unpack2(o2[i][0]);
        float2 p1 = unpack2(o2[i][1]);
        int row = b * T + t0 + r;
        *(float4*)&g_ctx[row * HDIM + h * DK + tx * 4] =
            make_float4(p0.x * inv, p0.y * inv, p1.x * inv, p1.y * inv);
    }
}

extern "C" void kernel_launch(void* const* d_in, const int* in_sizes, int n_in,
                              void* d_out, int out_size)
{
    const float* go   = (const float*)d_in[0];
    const float* node = (const float*)d_in[1];
    const float* Wq   = (const float*)d_in[2];
    const float* Wk   = (const float*)d_in[3];
    const float* Wv   = (const float*)d_in[4];
    const float* Wp   = (const float*)d_in[5];
    const int*   lens = (const int*)d_in[6];
    float* out = (float*)d_out;

    const int T = in_sizes[0] / HDIM;   // 1024
    const int N = in_sizes[1] / HDIM;   // 24576
    const int B = in_sizes[6];          // 16

    float *pQ, *pK, *pV, *pC;
    cudaGetSymbolAddress((void**)&pQ, g_Q);
    cudaGetSymbolAddress((void**)&pK, g_K);
    cudaGetSymbolAddress((void**)&pV, g_V);
    cudaGetSymbolAddress((void**)&pC, g_ctx);

    setup_kernel<<<1, 32>>>(lens, B, N);

    dim3 blk(256);
    gemm128<<<dim3(T / 128, 2), blk>>>(go, Wq, pQ);
    gemm128<<<dim3(N / 128, 2), blk>>>(node, Wk, pK);
    gemm128<<<dim3(N / 128, 2), blk>>>(node, Wv, pV);

    int smem = (2 * 64 * 132 + 128 * 68 + 128 * 132) * (int)sizeof(float);   // 169984 B
    cudaFuncSetAttribute(attn_kernel, cudaFuncAttributeMaxDynamicSharedMemorySize, smem);
    attn_kernel<<<dim3(T / 128, NHEADS, B), blk, smem>>>(T);

    gemm128<<<dim3((B * T) / 128, 2), blk>>>(pC, Wp, out);
}